// round 6
// baseline (speedup 1.0000x reference)
#include <cuda_runtime.h>
#include <math.h>

#define NN 65536
#define EE 1048576

// ---------------- scratch (device globals; no allocation allowed) ----------------
__device__ float g_h[NN * 64];      // encoded node features, row-major
__device__ float g_Sh[NN * 64];     // sum of h[src] over incoming edges, row-major
__device__ float g_h2[NN * 64];     // updated node features
__device__ float g_misc[NN * 4];    // {sum gx(src), sum gy(src), sum dist, pad}
__device__ int   g_deg[NN];
__device__ int   g_slots[NN * 64];  // incoming src lists, 64 slots per dst
__device__ int   g_flag;            // 0 => edge_index is int64, >0 => int32

__device__ __forceinline__ float gelu_f(float v) { return v * normcdff(v); }

// ---- packed fp32x2 helpers (SASS FFMA2 — only reachable via PTX) ----
typedef unsigned long long u64;
__device__ __forceinline__ u64 pack2(float a, float b) {
    u64 r; asm("mov.b64 %0,{%1,%2};" : "=l"(r) : "f"(a), "f"(b)); return r;
}
__device__ __forceinline__ u64 pack2s(float a) {  // splat
    u64 r; asm("mov.b64 %0,{%1,%1};" : "=l"(r) : "f"(a)); return r;
}
__device__ __forceinline__ void fma2(u64& d, u64 a, u64 b) {
    asm("fma.rn.f32x2 %0,%1,%2,%0;" : "+l"(d) : "l"(a), "l"(b));
}
__device__ __forceinline__ float2 unpack2(u64 v) {
    float2 r; asm("mov.b64 {%0,%1},%2;" : "=f"(r.x), "=f"(r.y) : "l"(v)); return r;
}

// ---------------- init: zero degrees + dtype-detect flag ----------------
__global__ void k_init(const long long* __restrict__ ei) {
    int i = blockIdx.x * blockDim.x + threadIdx.x;
    if (i < NN) g_deg[i] = 0;
    if (blockIdx.x == 0) {
        long long v = ei[threadIdx.x];
        unsigned bad = __ballot_sync(0xffffffffu, v < 0 || v >= NN);
        __shared__ int s;
        if (threadIdx.x == 0) s = 0;
        __syncthreads();
        if ((threadIdx.x & 31) == 0 && bad) atomicAdd(&s, 1);
        __syncthreads();
        if (threadIdx.x == 0) g_flag = s;
    }
}

// ---------------- encode: h = gelu(cat(x,grid)@W1 + b1) @ W2 + b2 ----------------
__global__ __launch_bounds__(128) void k_encode(
    const float* __restrict__ x, const float* __restrict__ grid,
    const float* __restrict__ W1, const float* __restrict__ b1,
    const float* __restrict__ W2, const float* __restrict__ b2) {
    __shared__ float sW1t[128 * 12];  // [m][f] transposed
    __shared__ float sB1[128];
    __shared__ float sW2[128 * 64];   // [m][o], rows 256B-aligned
    __shared__ float sB2[64];
    __shared__ float stgX[128 * 11];  // staged x rows, pad-11 (conflict-free)
    int base = blockIdx.x * 128;
    for (int i = threadIdx.x; i < 12 * 128; i += blockDim.x) {
        int f = i / 128, m = i % 128;
        sW1t[m * 12 + f] = W1[i];
    }
    for (int i = threadIdx.x; i < 128; i += blockDim.x) sB1[i] = b1[i];
    for (int i = threadIdx.x; i < 128 * 64; i += blockDim.x) sW2[i] = W2[i];
    for (int i = threadIdx.x; i < 64; i += blockDim.x) sB2[i] = b2[i];
    for (int q = threadIdx.x; q < 1280; q += blockDim.x)
        stgX[(q / 10) * 11 + (q % 10)] = x[base * 10 + q];   // coalesced
    __syncthreads();

    float in[12];
#pragma unroll
    for (int f = 0; f < 10; f++) in[f] = stgX[threadIdx.x * 11 + f];
    int node = base + threadIdx.x;
    float2 g = ((const float2*)grid)[node];
    in[10] = g.x; in[11] = g.y;

    u64 acc2[32];
#pragma unroll
    for (int o2 = 0; o2 < 32; o2++) acc2[o2] = pack2(sB2[2 * o2], sB2[2 * o2 + 1]);

    for (int m = 0; m < 128; m++) {
        float s = sB1[m];
#pragma unroll
        for (int f = 0; f < 12; f++) s += in[f] * sW1t[m * 12 + f];
        u64 gl2 = pack2s(gelu_f(s));
        const ulonglong2* w2r = (const ulonglong2*)&sW2[m * 64];
#pragma unroll
        for (int o4 = 0; o4 < 16; o4++) {
            ulonglong2 w = w2r[o4];
            fma2(acc2[o4 * 2 + 0], gl2, w.x);
            fma2(acc2[o4 * 2 + 1], gl2, w.y);
        }
    }
    float4* hp = (float4*)&g_h[node * 64];
#pragma unroll
    for (int o4 = 0; o4 < 16; o4++) {
        float2 a = unpack2(acc2[o4 * 2]), b = unpack2(acc2[o4 * 2 + 1]);
        hp[o4] = make_float4(a.x, a.y, b.x, b.y);
    }
}

// ---------------- scatter: bucket edges by destination (2 edges/thread) ----------------
__global__ void k_scatter(const long long* __restrict__ ei64) {
    int t = blockIdx.x * blockDim.x + threadIdx.x;
    int e = t * 2;
    if (e >= EE) return;
    int s0, d0, s1, d1;
    if (g_flag == 0) {
        longlong2 sv = ((const longlong2*)ei64)[t];
        longlong2 dv = ((const longlong2*)(ei64 + EE))[t];
        s0 = (int)sv.x; s1 = (int)sv.y;
        d0 = (int)dv.x; d1 = (int)dv.y;
    } else {
        const int2* ei32 = (const int2*)ei64;
        int2 sv = ei32[t];
        int2 dv = ei32[EE / 2 + t];
        s0 = sv.x; s1 = sv.y;
        d0 = dv.x; d1 = dv.y;
    }
    int p0 = atomicAdd(&g_deg[d0], 1);
    if (p0 < 64) g_slots[d0 * 64 + p0] = s0;
    int p1 = atomicAdd(&g_deg[d1], 1);
    if (p1 < 64) g_slots[d1 * 64 + p1] = s1;
}

// ---------------- aggregate: warp per dst, register accumulation ----------------
__global__ __launch_bounds__(256) void k_aggregate(const float* __restrict__ grid) {
    int gw = (blockIdx.x * blockDim.x + threadIdx.x) >> 5;
    int lane = threadIdx.x & 31;
    if (gw >= NN) return;
    int dst = gw;
    int d = g_deg[dst];
    if (d > 64) d = 64;
    float2 gi = ((const float2*)grid)[dst];
    float ax = 0.f, ay = 0.f, sgx = 0.f, sgy = 0.f, sd = 0.f;
    const int* slot = &g_slots[dst * 64];
    for (int k = 0; k < d; k++) {
        int src = slot[k];                                     // uniform (broadcast)
        float2 hv = *(const float2*)&g_h[src * 64 + 2 * lane]; // gather, L2-resident
        ax += hv.x; ay += hv.y;
        float2 gj = ((const float2*)grid)[src];
        sgx += gj.x; sgy += gj.y;
        float dx = gi.x - gj.x, dy = gi.y - gj.y;
        sd += sqrtf(dx * dx + dy * dy);
    }
    *(float2*)&g_Sh[dst * 64 + 2 * lane] = make_float2(ax, ay);
    if (lane == 0) {
        g_misc[dst * 4 + 0] = sgx;
        g_misc[dst * 4 + 1] = sgy;
        g_misc[dst * 4 + 2] = sd;
        g_misc[dst * 4 + 3] = 0.f;
    }
}

// ---------------- update: h2 = gelu(h@Ww + bw + aggr) (decomposed) ----------------
// aggr[i] = Σdist·Wk[0] + deg·(g_i@Wk[1:3]) + (Σg_j)@Wk[3:5]
//         + deg·(h_i@Wk[5:69]) + (Σh_j)@Wk[69:133] + deg·bk
#define UPD_SMEM_FLOATS (4096 * 3 + 320 + 64 + 64 + 2176 * 2)
__global__ __launch_bounds__(128) void k_update(
    const float* __restrict__ grid,
    const float* __restrict__ Wk, const float* __restrict__ bk,
    const float* __restrict__ Ww, const float* __restrict__ bw) {
    extern __shared__ float sm[];
    float* sWw  = sm;
    float* sWxi = sm + 4096;
    float* sWxj = sm + 8192;
    float* sGeo = sm + 12288;
    float* sBk  = sm + 12608;
    float* sBw  = sm + 12672;
    float* stgH = sm + 12736;
    float* stgS = sm + 14912;

    for (int i = threadIdx.x; i < 4096; i += blockDim.x) {
        sWw[i]  = Ww[i];
        sWxi[i] = Wk[5 * 64 + i];   // rows 5..68   (x_i block)
        sWxj[i] = Wk[69 * 64 + i];  // rows 69..132 (x_j block)
    }
    for (int i = threadIdx.x; i < 320; i += blockDim.x) sGeo[i] = Wk[i];  // rows 0..4
    for (int i = threadIdx.x; i < 64; i += blockDim.x) { sBk[i] = bk[i]; sBw[i] = bw[i]; }
    __syncthreads();

    int base = blockIdx.x * 128;
    int node = base + threadIdx.x;
    float fdeg = (float)g_deg[node];
    float4 misc = *(const float4*)&g_misc[node * 4];  // x=Σgx, y=Σgy, z=Σdist
    float2 gi = ((const float2*)grid)[node];

    u64 acc2[32];
#pragma unroll
    for (int o2 = 0; o2 < 32; o2++) {
        float a0, a1;
#pragma unroll
        for (int hh = 0; hh < 2; hh++) {
            int o = 2 * o2 + hh;
            float v = sBw[o] + fdeg * sBk[o]
                    + misc.z * sGeo[o]
                    + fdeg * gi.x * sGeo[64 + o] + fdeg * gi.y * sGeo[128 + o]
                    + misc.x * sGeo[192 + o] + misc.y * sGeo[256 + o];
            if (hh == 0) a0 = v; else a1 = v;
        }
        acc2[o2] = pack2(a0, a1);
    }

    for (int c = 0; c < 4; c++) {
        __syncthreads();
        for (int q = threadIdx.x; q < 2048; q += 128) {
            int r = q >> 4, jj = q & 15;
            int ga = (base + r) * 64 + c * 16 + jj;
            stgH[r * 17 + jj] = g_h[ga];
            stgS[r * 17 + jj] = g_Sh[ga];
        }
        __syncthreads();
        for (int jj = 0; jj < 16; jj++) {
            float hv = stgH[threadIdx.x * 17 + jj];
            float sv = stgS[threadIdx.x * 17 + jj];
            u64 hv2 = pack2s(hv);
            u64 dv2 = pack2s(fdeg * hv);
            u64 sv2 = pack2s(sv);
            int j = c * 16 + jj;
            const ulonglong2* wW = (const ulonglong2*)&sWw[j * 64];
            const ulonglong2* wI = (const ulonglong2*)&sWxi[j * 64];
            const ulonglong2* wJ = (const ulonglong2*)&sWxj[j * 64];
#pragma unroll
            for (int o4 = 0; o4 < 16; o4++) {
                ulonglong2 a = wW[o4], b = wI[o4], cc = wJ[o4];
                fma2(acc2[o4 * 2 + 0], hv2, a.x);
                fma2(acc2[o4 * 2 + 0], dv2, b.x);
                fma2(acc2[o4 * 2 + 0], sv2, cc.x);
                fma2(acc2[o4 * 2 + 1], hv2, a.y);
                fma2(acc2[o4 * 2 + 1], dv2, b.y);
                fma2(acc2[o4 * 2 + 1], sv2, cc.y);
            }
        }
    }
    float4* hp = (float4*)&g_h2[node * 64];
#pragma unroll
    for (int o4 = 0; o4 < 16; o4++) {
        float2 a = unpack2(acc2[o4 * 2]), b = unpack2(acc2[o4 * 2 + 1]);
        hp[o4] = make_float4(gelu_f(a.x), gelu_f(a.y), gelu_f(b.x), gelu_f(b.y));
    }
}

// ---------------- decode: out = gelu(h2@Wd1 + b1) @ Wd2 + b2 ----------------
__global__ __launch_bounds__(128) void k_decode(
    const float* __restrict__ Wd1, const float* __restrict__ bd1,
    const float* __restrict__ Wd2, const float* __restrict__ bd2,
    float* __restrict__ out) {
    __shared__ float sW[128 * 68];  // transposed [m][j], 16B-aligned rows
    __shared__ float sB1[128];
    __shared__ float sW2[128];
    __shared__ float stg[128 * 17];
    for (int i = threadIdx.x; i < 64 * 128; i += blockDim.x) {
        int j = i / 128, m = i % 128;
        sW[m * 68 + j] = Wd1[i];
    }
    for (int i = threadIdx.x; i < 128; i += blockDim.x) { sB1[i] = bd1[i]; sW2[i] = Wd2[i]; }
    __syncthreads();

    int base = blockIdx.x * 128;
    float h2[64];
#pragma unroll
    for (int c = 0; c < 4; c++) {
        __syncthreads();
        for (int q = threadIdx.x; q < 2048; q += 128) {
            int r = q >> 4, jj = q & 15;
            stg[r * 17 + jj] = g_h2[(base + r) * 64 + c * 16 + jj];
        }
        __syncthreads();
#pragma unroll
        for (int jj = 0; jj < 16; jj++) h2[c * 16 + jj] = stg[threadIdx.x * 17 + jj];
    }
    u64 hp2[32];
#pragma unroll
    for (int j2 = 0; j2 < 32; j2++) hp2[j2] = pack2(h2[2 * j2], h2[2 * j2 + 1]);

    float o = 0.f;
    for (int m = 0; m < 128; m++) {
        u64 s2 = pack2(sB1[m], 0.f);
        const ulonglong2* w = (const ulonglong2*)&sW[m * 68];
#pragma unroll
        for (int j4 = 0; j4 < 16; j4++) {
            ulonglong2 ww = w[j4];
            fma2(s2, hp2[j4 * 2 + 0], ww.x);
            fma2(s2, hp2[j4 * 2 + 1], ww.y);
        }
        float2 sv = unpack2(s2);
        o += gelu_f(sv.x + sv.y) * sW2[m];
    }
    out[base + threadIdx.x] = o + bd2[0];
}

// ---------------- launch ----------------
extern "C" void kernel_launch(void* const* d_in, const int* in_sizes, int n_in,
                              void* d_out, int out_size) {
    const float*     x    = (const float*)d_in[0];
    const float*     grid = (const float*)d_in[1];
    const long long* ei   = (const long long*)d_in[2];  // may really be int32; detected
    const float* W1  = (const float*)d_in[3];
    const float* b1  = (const float*)d_in[4];
    const float* W2  = (const float*)d_in[5];
    const float* b2  = (const float*)d_in[6];
    const float* Wk  = (const float*)d_in[7];
    const float* bk  = (const float*)d_in[8];
    const float* Ww  = (const float*)d_in[9];
    const float* bw  = (const float*)d_in[10];
    const float* Wd1 = (const float*)d_in[11];
    const float* bd1 = (const float*)d_in[12];
    const float* Wd2 = (const float*)d_in[13];
    const float* bd2 = (const float*)d_in[14];
    float* out = (float*)d_out;

    cudaFuncSetAttribute(k_update, cudaFuncAttributeMaxDynamicSharedMemorySize,
                         UPD_SMEM_FLOATS * (int)sizeof(float));

    k_init<<<NN / 256, 256>>>(ei);
    k_encode<<<NN / 128, 128>>>(x, grid, W1, b1, W2, b2);
    k_scatter<<<EE / 2 / 256, 256>>>(ei);
    k_aggregate<<<(NN * 32) / 256, 256>>>(grid);
    k_update<<<NN / 128, 128, UPD_SMEM_FLOATS * (int)sizeof(float)>>>(grid, Wk, bk, Ww, bw);
    k_decode<<<NN / 128, 128>>>(Wd1, bd1, Wd2, bd2, out);
}

// round 7
// speedup vs baseline: 1.5311x; 1.5311x over previous
#include <cuda_runtime.h>
#include <math.h>

#define NN 65536
#define EE 1048576

// ---------------- scratch (device globals; no allocation allowed) ----------------
__device__ float g_h[NN * 64];      // encoded node features, row-major
__device__ float g_Sh[NN * 64];     // sum of h[src] over incoming edges, row-major
__device__ float g_h2[NN * 64];     // updated node features
__device__ float g_misc[NN * 4];    // {sum gx(src), sum gy(src), sum dist, pad}
__device__ int   g_deg[NN];
__device__ int   g_slots[NN * 64];  // incoming src lists, 64 slots per dst
__device__ int   g_flag;            // 0 => edge_index is int64, >0 => int32

__device__ __forceinline__ float gelu_f(float v) {
    return 0.5f * v * (1.0f + erff(v * 0.70710678118654752440f));
}

// ---- packed fp32x2 helpers (SASS FFMA2 — only reachable via PTX) ----
typedef unsigned long long u64;
__device__ __forceinline__ u64 pack2(float a, float b) {
    u64 r; asm("mov.b64 %0,{%1,%2};" : "=l"(r) : "f"(a), "f"(b)); return r;
}
__device__ __forceinline__ u64 pack2s(float a) {  // splat
    u64 r; asm("mov.b64 %0,{%1,%1};" : "=l"(r) : "f"(a)); return r;
}
__device__ __forceinline__ void fma2(u64& d, u64 a, u64 b) {
    asm("fma.rn.f32x2 %0,%1,%2,%0;" : "+l"(d) : "l"(a), "l"(b));
}
__device__ __forceinline__ void add2(u64& d, u64 a) {
    asm("add.rn.f32x2 %0,%0,%1;" : "+l"(d) : "l"(a));
}
__device__ __forceinline__ float2 unpack2(u64 v) {
    float2 r; asm("mov.b64 {%0,%1},%2;" : "=f"(r.x), "=f"(r.y) : "l"(v)); return r;
}

// ---------------- init: zero degrees + dtype-detect flag ----------------
__global__ void k_init(const long long* __restrict__ ei) {
    int i = blockIdx.x * blockDim.x + threadIdx.x;
    if (i < NN) g_deg[i] = 0;
    if (blockIdx.x == 0) {
        long long v = ei[threadIdx.x];
        unsigned bad = __ballot_sync(0xffffffffu, v < 0 || v >= NN);
        __shared__ int s;
        if (threadIdx.x == 0) s = 0;
        __syncthreads();
        if ((threadIdx.x & 31) == 0 && bad) atomicAdd(&s, 1);
        __syncthreads();
        if (threadIdx.x == 0) g_flag = s;
    }
}

// ============================================================================
// encode: h = gelu(cat(x,grid)@W1 + b1) @ W2 + b2   as tiled GEMM
// block = 128 nodes, 256 threads: tx=tid&15 (4-out quad), ty=tid>>4 (8-node octet)
// smem floats: sXt[12*132] sW1[12*128] sW2[128*64] sB1[128] sB2[64] sH[128*68]
// ============================================================================
#define ENC_SMEM_BYTES ((1584 + 1536 + 8192 + 128 + 64 + 8704) * 4)
__global__ __launch_bounds__(256) void k_encode(
    const float* __restrict__ x, const float* __restrict__ grid,
    const float* __restrict__ W1, const float* __restrict__ b1,
    const float* __restrict__ W2, const float* __restrict__ b2) {
    extern __shared__ float sm[];
    float* sXt = sm;            // [12][132] transposed inputs
    float* sW1 = sm + 1584;     // [12][128]
    float* sW2 = sm + 3120;     // [128][64]
    float* sB1 = sm + 11312;    // [128]
    float* sB2 = sm + 11440;    // [64]
    float* sH  = sm + 11504;    // [128][68] hidden half (gelu'd)

    int tid = threadIdx.x;
    int base = blockIdx.x * 128;
    for (int i = tid; i < 1280; i += 256) {
        int n = i / 10, f = i % 10;
        sXt[f * 132 + n] = x[base * 10 + i];
    }
    if (tid < 128) {
        float2 g = ((const float2*)grid)[base + tid];
        sXt[10 * 132 + tid] = g.x;
        sXt[11 * 132 + tid] = g.y;
    }
    for (int i = tid; i < 12 * 128; i += 256) sW1[i] = W1[i];
    for (int i = tid; i < 128 * 64; i += 256) sW2[i] = W2[i];
    if (tid < 128) sB1[tid] = b1[tid];
    if (tid < 64) sB2[tid] = b2[tid];
    __syncthreads();

    int tx = tid & 15, ty = tid >> 4;

    u64 accO[8][2];  // [8 nodes][2 out-pairs], outs 4*tx..4*tx+3
#pragma unroll
    for (int i = 0; i < 8; i++) {
        accO[i][0] = pack2(sB2[4 * tx], sB2[4 * tx + 1]);
        accO[i][1] = pack2(sB2[4 * tx + 2], sB2[4 * tx + 3]);
    }

    for (int p = 0; p < 2; p++) {
        int mb = 64 * p;
        u64 acc1[8][2];  // mids mb+4tx..+3
#pragma unroll
        for (int i = 0; i < 8; i++) {
            acc1[i][0] = pack2(sB1[mb + 4 * tx], sB1[mb + 4 * tx + 1]);
            acc1[i][1] = pack2(sB1[mb + 4 * tx + 2], sB1[mb + 4 * tx + 3]);
        }
#pragma unroll
        for (int k = 0; k < 12; k++) {
            float4 a0 = *(const float4*)&sXt[k * 132 + 8 * ty];
            float4 a1 = *(const float4*)&sXt[k * 132 + 8 * ty + 4];
            ulonglong2 w = *(const ulonglong2*)&sW1[k * 128 + mb + 4 * tx];
            float av[8] = {a0.x, a0.y, a0.z, a0.w, a1.x, a1.y, a1.z, a1.w};
#pragma unroll
            for (int i = 0; i < 8; i++) {
                u64 s = pack2s(av[i]);
                fma2(acc1[i][0], s, w.x);
                fma2(acc1[i][1], s, w.y);
            }
        }
        __syncthreads();   // previous pass's sH readers done before overwrite
#pragma unroll
        for (int i = 0; i < 8; i++) {
            float2 lo = unpack2(acc1[i][0]), hi = unpack2(acc1[i][1]);
            *(float4*)&sH[(8 * ty + i) * 68 + 4 * tx] =
                make_float4(gelu_f(lo.x), gelu_f(lo.y), gelu_f(hi.x), gelu_f(hi.y));
        }
        __syncthreads();
#pragma unroll 4
        for (int k = 0; k < 64; k++) {
            ulonglong2 w = *(const ulonglong2*)&sW2[(mb + k) * 64 + 4 * tx];
#pragma unroll
            for (int i = 0; i < 8; i++) {
                u64 s = pack2s(sH[(8 * ty + i) * 68 + k]);
                fma2(accO[i][0], s, w.x);
                fma2(accO[i][1], s, w.y);
            }
        }
    }
#pragma unroll
    for (int i = 0; i < 8; i++) {
        float2 lo = unpack2(accO[i][0]), hi = unpack2(accO[i][1]);
        *(float4*)&g_h[(base + 8 * ty + i) * 64 + 4 * tx] =
            make_float4(lo.x, lo.y, hi.x, hi.y);
    }
}

// ---------------- scatter: bucket edges by destination (2 edges/thread) ----------------
__global__ void k_scatter(const long long* __restrict__ ei64) {
    int t = blockIdx.x * blockDim.x + threadIdx.x;
    int e = t * 2;
    if (e >= EE) return;
    int s0, d0, s1, d1;
    if (g_flag == 0) {
        longlong2 sv = ((const longlong2*)ei64)[t];
        longlong2 dv = ((const longlong2*)(ei64 + EE))[t];
        s0 = (int)sv.x; s1 = (int)sv.y;
        d0 = (int)dv.x; d1 = (int)dv.y;
    } else {
        const int2* ei32 = (const int2*)ei64;
        int2 sv = ei32[t];
        int2 dv = ei32[EE / 2 + t];
        s0 = sv.x; s1 = sv.y;
        d0 = dv.x; d1 = dv.y;
    }
    int p0 = atomicAdd(&g_deg[d0], 1);
    if (p0 < 64) g_slots[d0 * 64 + p0] = s0;
    int p1 = atomicAdd(&g_deg[d1], 1);
    if (p1 < 64) g_slots[d1 * 64 + p1] = s1;
}

// ---------------- aggregate: warp per dst, register accumulation ----------------
__global__ __launch_bounds__(256) void k_aggregate(const float* __restrict__ grid) {
    int gw = (blockIdx.x * blockDim.x + threadIdx.x) >> 5;
    int lane = threadIdx.x & 31;
    if (gw >= NN) return;
    int dst = gw;
    int d = g_deg[dst];
    if (d > 64) d = 64;
    float2 gi = ((const float2*)grid)[dst];
    float ax = 0.f, ay = 0.f, sgx = 0.f, sgy = 0.f, sd = 0.f;
    const int* slot = &g_slots[dst * 64];
    for (int k = 0; k < d; k++) {
        int src = slot[k];                                     // uniform (broadcast)
        float2 hv = *(const float2*)&g_h[src * 64 + 2 * lane]; // gather, L2-resident
        ax += hv.x; ay += hv.y;
        float2 gj = ((const float2*)grid)[src];
        sgx += gj.x; sgy += gj.y;
        float dx = gi.x - gj.x, dy = gi.y - gj.y;
        sd += sqrtf(dx * dx + dy * dy);
    }
    *(float2*)&g_Sh[dst * 64 + 2 * lane] = make_float2(ax, ay);
    if (lane == 0) {
        g_misc[dst * 4 + 0] = sgx;
        g_misc[dst * 4 + 1] = sgy;
        g_misc[dst * 4 + 2] = sd;
        g_misc[dst * 4 + 3] = 0.f;
    }
}

// ============================================================================
// update: h2 = gelu(h@Ww + deg*(h@Wxi) + Sh@Wxj + affine(geo,deg))  as tiled GEMM
// block = 128 nodes, 256 threads, thread tile 8 nodes x 4 outs
// smem floats: sWw[4096] sWxi[4096] sWxj[4096] sGeoB[7*64] sCoef[128*8] sA[32*132]
// ============================================================================
#define UPD_SMEM_BYTES ((4096 * 3 + 448 + 1024 + 4224) * 4)
__global__ __launch_bounds__(256, 2) void k_update(
    const float* __restrict__ grid,
    const float* __restrict__ Wk, const float* __restrict__ bk,
    const float* __restrict__ Ww, const float* __restrict__ bw) {
    extern __shared__ float sm[];
    float* sWw   = sm;             // [64][64]
    float* sWxi  = sm + 4096;      // [64][64]
    float* sWxj  = sm + 8192;      // [64][64]
    float* sGeoB = sm + 12288;     // [7][64]: geo rows 0..4, bk, bw
    float* sCoef = sm + 12736;     // [128][8]: {fdeg, mz, fdeg*gx, fdeg*gy, mx, my}
    float* sA    = sm + 13760;     // [32][132] transposed chunk staging

    int tid = threadIdx.x;
    int base = blockIdx.x * 128;
    for (int i = tid; i < 4096; i += 256) {
        sWw[i]  = Ww[i];
        sWxi[i] = Wk[5 * 64 + i];
        sWxj[i] = Wk[69 * 64 + i];
    }
    for (int i = tid; i < 320; i += 256) sGeoB[i] = Wk[i];
    if (tid < 64) { sGeoB[320 + tid] = bk[tid]; sGeoB[384 + tid] = bw[tid]; }
    if (tid < 128) {
        int node = base + tid;
        float fdeg = (float)g_deg[node];
        float4 m = *(const float4*)&g_misc[node * 4];
        float2 gi = ((const float2*)grid)[node];
        float* c = &sCoef[tid * 8];
        c[0] = fdeg; c[1] = m.z; c[2] = fdeg * gi.x; c[3] = fdeg * gi.y;
        c[4] = m.x;  c[5] = m.y;
    }

    int tx = tid & 15, ty = tid >> 4;
    u64 C13[8][2], C2[8][2];
#pragma unroll
    for (int i = 0; i < 8; i++) {
        C13[i][0] = C13[i][1] = pack2s(0.f);
        C2[i][0]  = C2[i][1]  = pack2s(0.f);
    }

    for (int pass = 0; pass < 4; pass++) {
        const float* src = (pass < 2) ? g_h : g_Sh;
        int koff = (pass & 1) * 32;
        __syncthreads();
        // stage 32 k x 128 n transposed
        for (int it = 0; it < 4; it++) {
            int f4 = tid + 256 * it;
            int n = f4 >> 3, kk = f4 & 7;
            float4 v = *(const float4*)&src[(base + n) * 64 + koff + 4 * kk];
            float* dst = &sA[(4 * kk) * 132 + n];
            dst[0] = v.x; dst[132] = v.y; dst[264] = v.z; dst[396] = v.w;
        }
        __syncthreads();
        int kg0 = koff;
        if (pass < 2) {
#pragma unroll 4
            for (int k = 0; k < 32; k++) {
                float4 a0 = *(const float4*)&sA[k * 132 + 8 * ty];
                float4 a1 = *(const float4*)&sA[k * 132 + 8 * ty + 4];
                ulonglong2 wW = *(const ulonglong2*)&sWw[(kg0 + k) * 64 + 4 * tx];
                ulonglong2 wI = *(const ulonglong2*)&sWxi[(kg0 + k) * 64 + 4 * tx];
                float av[8] = {a0.x, a0.y, a0.z, a0.w, a1.x, a1.y, a1.z, a1.w};
#pragma unroll
                for (int i = 0; i < 8; i++) {
                    u64 s = pack2s(av[i]);
                    fma2(C13[i][0], s, wW.x);
                    fma2(C13[i][1], s, wW.y);
                    fma2(C2[i][0],  s, wI.x);
                    fma2(C2[i][1],  s, wI.y);
                }
            }
        } else {
#pragma unroll 4
            for (int k = 0; k < 32; k++) {
                float4 a0 = *(const float4*)&sA[k * 132 + 8 * ty];
                float4 a1 = *(const float4*)&sA[k * 132 + 8 * ty + 4];
                ulonglong2 wJ = *(const ulonglong2*)&sWxj[(kg0 + k) * 64 + 4 * tx];
                float av[8] = {a0.x, a0.y, a0.z, a0.w, a1.x, a1.y, a1.z, a1.w};
#pragma unroll
                for (int i = 0; i < 8; i++) {
                    u64 s = pack2s(av[i]);
                    fma2(C13[i][0], s, wJ.x);
                    fma2(C13[i][1], s, wJ.y);
                }
            }
        }
    }

    // epilogue: affine terms + fdeg*C2, gelu, store
    ulonglong2 G[7];
#pragma unroll
    for (int p = 0; p < 7; p++) G[p] = *(const ulonglong2*)&sGeoB[p * 64 + 4 * tx];
#pragma unroll
    for (int i = 0; i < 8; i++) {
        const float* c = &sCoef[(8 * ty + i) * 8];
        u64 fd = pack2s(c[0]), mz = pack2s(c[1]), fgx = pack2s(c[2]),
            fgy = pack2s(c[3]), mx = pack2s(c[4]), my = pack2s(c[5]);
        u64 d0 = C13[i][0], d1 = C13[i][1];
        add2(d0, G[6].x);        add2(d1, G[6].y);        // bw
        fma2(d0, fd, G[5].x);    fma2(d1, fd, G[5].y);    // fdeg*bk
        fma2(d0, fd, C2[i][0]);  fma2(d1, fd, C2[i][1]);  // fdeg*(h@Wxi)
        fma2(d0, mz, G[0].x);    fma2(d1, mz, G[0].y);    // Σdist * geo0
        fma2(d0, fgx, G[1].x);   fma2(d1, fgx, G[1].y);
        fma2(d0, fgy, G[2].x);   fma2(d1, fgy, G[2].y);
        fma2(d0, mx, G[3].x);    fma2(d1, mx, G[3].y);
        fma2(d0, my, G[4].x);    fma2(d1, my, G[4].y);
        float2 lo = unpack2(d0), hi = unpack2(d1);
        *(float4*)&g_h2[(base + 8 * ty + i) * 64 + 4 * tx] =
            make_float4(gelu_f(lo.x), gelu_f(lo.y), gelu_f(hi.x), gelu_f(hi.y));
    }
}

// ============================================================================
// decode: out = gelu(h2@Wd1 + b1) @ Wd2 + b2   as tiled GEMM + reduction
// block = 128 nodes, 256 threads, thread tile 8 nodes x 8 mids
// smem floats: sAt[64*132] sW[64*128] sB1[128] sW2v[128] sRed[128*17]
// ============================================================================
#define DEC_SMEM_BYTES ((8448 + 8192 + 128 + 128 + 2176) * 4)
__global__ __launch_bounds__(256, 2) void k_decode(
    const float* __restrict__ Wd1, const float* __restrict__ bd1,
    const float* __restrict__ Wd2, const float* __restrict__ bd2,
    float* __restrict__ out) {
    extern __shared__ float sm[];
    float* sAt  = sm;           // [64][132] h2 transposed
    float* sW   = sm + 8448;    // [64][128]
    float* sB1  = sm + 16640;
    float* sW2v = sm + 16768;
    float* sRed = sm + 16896;   // [128][17]

    int tid = threadIdx.x;
    int base = blockIdx.x * 128;
    for (int it = 0; it < 8; it++) {
        int f4 = tid + 256 * it;
        int n = f4 >> 4, kk = f4 & 15;
        float4 v = *(const float4*)&g_h2[(base + n) * 64 + 4 * kk];
        float* dst = &sAt[(4 * kk) * 132 + n];
        dst[0] = v.x; dst[132] = v.y; dst[264] = v.z; dst[396] = v.w;
    }
    for (int i = tid; i < 8192; i += 256) sW[i] = Wd1[i];
    if (tid < 128) { sB1[tid] = bd1[tid]; sW2v[tid] = Wd2[tid]; }
    __syncthreads();

    int tx = tid & 15, ty = tid >> 4;
    u64 acc[8][4];  // [8 nodes][4 mid-pairs], mids 8*tx..8*tx+7
#pragma unroll
    for (int i = 0; i < 8; i++)
#pragma unroll
        for (int j = 0; j < 4; j++) acc[i][j] = pack2s(0.f);

#pragma unroll 4
    for (int k = 0; k < 64; k++) {
        float4 a0 = *(const float4*)&sAt[k * 132 + 8 * ty];
        float4 a1 = *(const float4*)&sAt[k * 132 + 8 * ty + 4];
        ulonglong2 w0 = *(const ulonglong2*)&sW[k * 128 + 8 * tx];
        ulonglong2 w1 = *(const ulonglong2*)&sW[k * 128 + 8 * tx + 4];
        float av[8] = {a0.x, a0.y, a0.z, a0.w, a1.x, a1.y, a1.z, a1.w};
#pragma unroll
        for (int i = 0; i < 8; i++) {
            u64 s = pack2s(av[i]);
            fma2(acc[i][0], s, w0.x);
            fma2(acc[i][1], s, w0.y);
            fma2(acc[i][2], s, w1.x);
            fma2(acc[i][3], s, w1.y);
        }
    }

    float b[8], w2[8];
#pragma unroll
    for (int j = 0; j < 8; j++) { b[j] = sB1[8 * tx + j]; w2[j] = sW2v[8 * tx + j]; }
#pragma unroll
    for (int i = 0; i < 8; i++) {
        float part = 0.f;
#pragma unroll
        for (int j = 0; j < 4; j++) {
            float2 v = unpack2(acc[i][j]);
            part += gelu_f(v.x + b[2 * j]) * w2[2 * j];
            part += gelu_f(v.y + b[2 * j + 1]) * w2[2 * j + 1];
        }
        sRed[(8 * ty + i) * 17 + tx] = part;
    }
    __syncthreads();
    if (tid < 128) {
        float s = 0.f;
        const float* r = &sRed[tid * 17];
#pragma unroll
        for (int t = 0; t < 16; t++) s += r[t];
        out[base + tid] = s + bd2[0];
    }
}

// ---------------- launch ----------------
extern "C" void kernel_launch(void* const* d_in, const int* in_sizes, int n_in,
                              void* d_out, int out_size) {
    const float*     x    = (const float*)d_in[0];
    const float*     grid = (const float*)d_in[1];
    const long long* ei   = (const long long*)d_in[2];  // may really be int32; detected
    const float* W1  = (const float*)d_in[3];
    const float* b1  = (const float*)d_in[4];
    const float* W2  = (const float*)d_in[5];
    const float* b2  = (const float*)d_in[6];
    const float* Wk  = (const float*)d_in[7];
    const float* bk  = (const float*)d_in[8];
    const float* Ww  = (const float*)d_in[9];
    const float* bw  = (const float*)d_in[10];
    const float* Wd1 = (const float*)d_in[11];
    const float* bd1 = (const float*)d_in[12];
    const float* Wd2 = (const float*)d_in[13];
    const float* bd2 = (const float*)d_in[14];
    float* out = (float*)d_out;

    cudaFuncSetAttribute(k_encode, cudaFuncAttributeMaxDynamicSharedMemorySize, ENC_SMEM_BYTES);
    cudaFuncSetAttribute(k_update, cudaFuncAttributeMaxDynamicSharedMemorySize, UPD_SMEM_BYTES);
    cudaFuncSetAttribute(k_decode, cudaFuncAttributeMaxDynamicSharedMemorySize, DEC_SMEM_BYTES);

    k_init<<<NN / 256, 256>>>(ei);
    k_encode<<<NN / 128, 256, ENC_SMEM_BYTES>>>(x, grid, W1, b1, W2, b2);
    k_scatter<<<EE / 2 / 256, 256>>>(ei);
    k_aggregate<<<(NN * 32) / 256, 256>>>(grid);
    k_update<<<NN / 128, 256, UPD_SMEM_BYTES>>>(grid, Wk, bk, Ww, bw);
    k_decode<<<NN / 128, 256, DEC_SMEM_BYTES>>>(Wd1, bd1, Wd2, bd2, out);
}

// round 8
// speedup vs baseline: 1.6952x; 1.1072x over previous
#include <cuda_runtime.h>
#include <math.h>

#define NN 65536
#define EE 1048576

// ---------------- scratch (device globals; no allocation allowed) ----------------
__device__ float g_h[NN * 64];      // encoded node features, row-major
__device__ float g_Sh[NN * 64];     // sum of h[src] over incoming edges, row-major
__device__ float g_h2[NN * 64];     // updated node features
__device__ float g_misc[NN * 4];    // {sum gx(src), sum gy(src), sum dist, pad}
__device__ int   g_deg[NN];
__device__ int   g_slots[NN * 64];  // incoming src lists, 64 slots per dst
__device__ int   g_flag;            // 0 => edge_index is int64, >0 => int32

__device__ __forceinline__ float gelu_f(float v) {
    return 0.5f * v * (1.0f + erff(v * 0.70710678118654752440f));
}

// ---- packed fp32x2 helpers (SASS FFMA2 — only reachable via PTX) ----
typedef unsigned long long u64;
__device__ __forceinline__ u64 pack2(float a, float b) {
    u64 r; asm("mov.b64 %0,{%1,%2};" : "=l"(r) : "f"(a), "f"(b)); return r;
}
__device__ __forceinline__ u64 pack2s(float a) {  // splat
    u64 r; asm("mov.b64 %0,{%1,%1};" : "=l"(r) : "f"(a)); return r;
}
__device__ __forceinline__ void fma2(u64& d, u64 a, u64 b) {
    asm("fma.rn.f32x2 %0,%1,%2,%0;" : "+l"(d) : "l"(a), "l"(b));
}
__device__ __forceinline__ void add2(u64& d, u64 a) {
    asm("add.rn.f32x2 %0,%0,%1;" : "+l"(d) : "l"(a));
}
__device__ __forceinline__ float2 unpack2(u64 v) {
    float2 r; asm("mov.b64 {%0,%1},%2;" : "=f"(r.x), "=f"(r.y) : "l"(v)); return r;
}

// ---------------- init: zero degrees + dtype-detect flag ----------------
__global__ void k_init(const long long* __restrict__ ei) {
    int i = blockIdx.x * blockDim.x + threadIdx.x;
    if (i < NN) g_deg[i] = 0;
    if (blockIdx.x == 0) {
        long long v = ei[threadIdx.x];
        unsigned bad = __ballot_sync(0xffffffffu, v < 0 || v >= NN);
        __shared__ int s;
        if (threadIdx.x == 0) s = 0;
        __syncthreads();
        if ((threadIdx.x & 31) == 0 && bad) atomicAdd(&s, 1);
        __syncthreads();
        if (threadIdx.x == 0) g_flag = s;
    }
}

// ============================================================================
// encode: h = gelu(cat(x,grid)@W1 + b1) @ W2 + b2   as tiled GEMM
// ============================================================================
#define ENC_SMEM_BYTES ((1584 + 1536 + 8192 + 128 + 64 + 8704) * 4)
__global__ __launch_bounds__(256) void k_encode(
    const float* __restrict__ x, const float* __restrict__ grid,
    const float* __restrict__ W1, const float* __restrict__ b1,
    const float* __restrict__ W2, const float* __restrict__ b2) {
    extern __shared__ float sm[];
    float* sXt = sm;            // [12][132] transposed inputs
    float* sW1 = sm + 1584;     // [12][128]
    float* sW2 = sm + 3120;     // [128][64]
    float* sB1 = sm + 11312;    // [128]
    float* sB2 = sm + 11440;    // [64]
    float* sH  = sm + 11504;    // [128][68] hidden half (gelu'd)

    int tid = threadIdx.x;
    int base = blockIdx.x * 128;
    for (int i = tid; i < 1280; i += 256) {
        int n = i / 10, f = i % 10;
        sXt[f * 132 + n] = x[base * 10 + i];
    }
    if (tid < 128) {
        float2 g = ((const float2*)grid)[base + tid];
        sXt[10 * 132 + tid] = g.x;
        sXt[11 * 132 + tid] = g.y;
    }
    for (int i = tid; i < 12 * 128; i += 256) sW1[i] = W1[i];
    for (int i = tid; i < 128 * 64; i += 256) sW2[i] = W2[i];
    if (tid < 128) sB1[tid] = b1[tid];
    if (tid < 64) sB2[tid] = b2[tid];
    __syncthreads();

    int tx = tid & 15, ty = tid >> 4;

    u64 accO[8][2];  // [8 nodes][2 out-pairs], outs 4*tx..4*tx+3
#pragma unroll
    for (int i = 0; i < 8; i++) {
        accO[i][0] = pack2(sB2[4 * tx], sB2[4 * tx + 1]);
        accO[i][1] = pack2(sB2[4 * tx + 2], sB2[4 * tx + 3]);
    }

    for (int p = 0; p < 2; p++) {
        int mb = 64 * p;
        u64 acc1[8][2];  // mids mb+4tx..+3
#pragma unroll
        for (int i = 0; i < 8; i++) {
            acc1[i][0] = pack2(sB1[mb + 4 * tx], sB1[mb + 4 * tx + 1]);
            acc1[i][1] = pack2(sB1[mb + 4 * tx + 2], sB1[mb + 4 * tx + 3]);
        }
#pragma unroll
        for (int k = 0; k < 12; k++) {
            float4 a0 = *(const float4*)&sXt[k * 132 + 8 * ty];
            float4 a1 = *(const float4*)&sXt[k * 132 + 8 * ty + 4];
            ulonglong2 w = *(const ulonglong2*)&sW1[k * 128 + mb + 4 * tx];
            float av[8] = {a0.x, a0.y, a0.z, a0.w, a1.x, a1.y, a1.z, a1.w};
#pragma unroll
            for (int i = 0; i < 8; i++) {
                u64 s = pack2s(av[i]);
                fma2(acc1[i][0], s, w.x);
                fma2(acc1[i][1], s, w.y);
            }
        }
        __syncthreads();   // previous pass's sH readers done before overwrite
#pragma unroll
        for (int i = 0; i < 8; i++) {
            float2 lo = unpack2(acc1[i][0]), hi = unpack2(acc1[i][1]);
            *(float4*)&sH[(8 * ty + i) * 68 + 4 * tx] =
                make_float4(gelu_f(lo.x), gelu_f(lo.y), gelu_f(hi.x), gelu_f(hi.y));
        }
        __syncthreads();
#pragma unroll 4
        for (int k = 0; k < 64; k++) {
            ulonglong2 w = *(const ulonglong2*)&sW2[(mb + k) * 64 + 4 * tx];
#pragma unroll
            for (int i = 0; i < 8; i++) {
                u64 s = pack2s(sH[(8 * ty + i) * 68 + k]);
                fma2(accO[i][0], s, w.x);
                fma2(accO[i][1], s, w.y);
            }
        }
    }
#pragma unroll
    for (int i = 0; i < 8; i++) {
        float2 lo = unpack2(accO[i][0]), hi = unpack2(accO[i][1]);
        *(float4*)&g_h[(base + 8 * ty + i) * 64 + 4 * tx] =
            make_float4(lo.x, lo.y, hi.x, hi.y);
    }
}

// ---------------- scatter: bucket edges by destination (2 edges/thread) ----------------
__global__ void k_scatter(const long long* __restrict__ ei64) {
    int t = blockIdx.x * blockDim.x + threadIdx.x;
    int e = t * 2;
    if (e >= EE) return;
    int s0, d0, s1, d1;
    if (g_flag == 0) {
        longlong2 sv = ((const longlong2*)ei64)[t];
        longlong2 dv = ((const longlong2*)(ei64 + EE))[t];
        s0 = (int)sv.x; s1 = (int)sv.y;
        d0 = (int)dv.x; d1 = (int)dv.y;
    } else {
        const int2* ei32 = (const int2*)ei64;
        int2 sv = ei32[t];
        int2 dv = ei32[EE / 2 + t];
        s0 = sv.x; s1 = sv.y;
        d0 = dv.x; d1 = dv.y;
    }
    int p0 = atomicAdd(&g_deg[d0], 1);
    if (p0 < 64) g_slots[d0 * 64 + p0] = s0;
    int p1 = atomicAdd(&g_deg[d1], 1);
    if (p1 < 64) g_slots[d1 * 64 + p1] = s1;
}

// ============================================================================
// aggregate: warp per dst. Slots loaded lane-parallel + smem-staged; geo math
// distributed across lanes (1 lane per edge) + butterfly reduce; h-gather at
// 2 edges/iteration (half-warp float4 each), 2-deep unroll for MLP.
// ============================================================================
__global__ __launch_bounds__(256) void k_aggregate(const float* __restrict__ grid) {
    __shared__ int sSlot[8 * 64];
    int wib = threadIdx.x >> 5;                      // warp in block (0..7)
    int gw = (blockIdx.x * blockDim.x + threadIdx.x) >> 5;
    int lane = threadIdx.x & 31;
    int dst = gw;
    int d = g_deg[dst];
    if (d > 64) d = 64;

    // ---- slots: 2 coalesced loads per warp, staged to smem ----
    int s0 = (lane < d) ? g_slots[dst * 64 + lane] : -1;
    int s1 = (lane + 32 < d) ? g_slots[dst * 64 + 32 + lane] : -1;
    int* mySlot = &sSlot[wib * 64];
    mySlot[lane] = s0;
    mySlot[lane + 32] = s1;
    __syncwarp();

    // ---- geometry: lane k handles edge k (distributed, not redundant) ----
    float2 gi = ((const float2*)grid)[dst];
    float sgx = 0.f, sgy = 0.f, sd = 0.f;
    if (s0 >= 0) {
        float2 gj = ((const float2*)grid)[s0];
        sgx += gj.x; sgy += gj.y;
        float dx = gi.x - gj.x, dy = gi.y - gj.y;
        sd += sqrtf(dx * dx + dy * dy);
    }
    if (s1 >= 0) {
        float2 gj = ((const float2*)grid)[s1];
        sgx += gj.x; sgy += gj.y;
        float dx = gi.x - gj.x, dy = gi.y - gj.y;
        sd += sqrtf(dx * dx + dy * dy);
    }
#pragma unroll
    for (int off = 16; off; off >>= 1) {
        sgx += __shfl_xor_sync(0xffffffffu, sgx, off);
        sgy += __shfl_xor_sync(0xffffffffu, sgy, off);
        sd  += __shfl_xor_sync(0xffffffffu, sd,  off);
    }
    if (lane == 0) {
        g_misc[dst * 4 + 0] = sgx;
        g_misc[dst * 4 + 1] = sgy;
        g_misc[dst * 4 + 2] = sd;
        g_misc[dst * 4 + 3] = 0.f;
    }

    // ---- h gather: half-warp per edge, float4 per lane (256B/edge) ----
    int half = lane >> 4;        // 0 or 1
    int l16 = lane & 15;
    float4 a0 = make_float4(0.f, 0.f, 0.f, 0.f);
    float4 a1 = make_float4(0.f, 0.f, 0.f, 0.f);
    int k = half;
    for (; k + 2 < d; k += 4) {
        int srcA = mySlot[k];
        int srcB = mySlot[k + 2];
        float4 hA = *(const float4*)&g_h[srcA * 64 + 4 * l16];
        float4 hB = *(const float4*)&g_h[srcB * 64 + 4 * l16];
        a0.x += hA.x; a0.y += hA.y; a0.z += hA.z; a0.w += hA.w;
        a1.x += hB.x; a1.y += hB.y; a1.z += hB.z; a1.w += hB.w;
    }
    for (; k < d; k += 2) {
        int srcA = mySlot[k];
        float4 hA = *(const float4*)&g_h[srcA * 64 + 4 * l16];
        a0.x += hA.x; a0.y += hA.y; a0.z += hA.z; a0.w += hA.w;
    }
    a0.x += a1.x; a0.y += a1.y; a0.z += a1.z; a0.w += a1.w;
    // combine halves (lane L += lane L+16)
    a0.x += __shfl_xor_sync(0xffffffffu, a0.x, 16);
    a0.y += __shfl_xor_sync(0xffffffffu, a0.y, 16);
    a0.z += __shfl_xor_sync(0xffffffffu, a0.z, 16);
    a0.w += __shfl_xor_sync(0xffffffffu, a0.w, 16);
    if (half == 0)
        *(float4*)&g_Sh[dst * 64 + 4 * l16] = a0;
}

// ============================================================================
// update: h2 = gelu(h@Ww + deg*(h@Wxi) + Sh@Wxj + affine(geo,deg))  as tiled GEMM
// ============================================================================
#define UPD_SMEM_BYTES ((4096 * 3 + 448 + 1024 + 4224) * 4)
__global__ __launch_bounds__(256, 2) void k_update(
    const float* __restrict__ grid,
    const float* __restrict__ Wk, const float* __restrict__ bk,
    const float* __restrict__ Ww, const float* __restrict__ bw) {
    extern __shared__ float sm[];
    float* sWw   = sm;             // [64][64]
    float* sWxi  = sm + 4096;      // [64][64]
    float* sWxj  = sm + 8192;      // [64][64]
    float* sGeoB = sm + 12288;     // [7][64]: geo rows 0..4, bk, bw
    float* sCoef = sm + 12736;     // [128][8]: {fdeg, mz, fdeg*gx, fdeg*gy, mx, my}
    float* sA    = sm + 13760;     // [32][132] transposed chunk staging

    int tid = threadIdx.x;
    int base = blockIdx.x * 128;
    for (int i = tid; i < 4096; i += 256) {
        sWw[i]  = Ww[i];
        sWxi[i] = Wk[5 * 64 + i];
        sWxj[i] = Wk[69 * 64 + i];
    }
    for (int i = tid; i < 320; i += 256) sGeoB[i] = Wk[i];
    if (tid < 64) { sGeoB[320 + tid] = bk[tid]; sGeoB[384 + tid] = bw[tid]; }
    if (tid < 128) {
        int node = base + tid;
        float fdeg = (float)g_deg[node];
        float4 m = *(const float4*)&g_misc[node * 4];
        float2 gi = ((const float2*)grid)[node];
        float* c = &sCoef[tid * 8];
        c[0] = fdeg; c[1] = m.z; c[2] = fdeg * gi.x; c[3] = fdeg * gi.y;
        c[4] = m.x;  c[5] = m.y;
    }

    int tx = tid & 15, ty = tid >> 4;
    u64 C13[8][2], C2[8][2];
#pragma unroll
    for (int i = 0; i < 8; i++) {
        C13[i][0] = C13[i][1] = pack2s(0.f);
        C2[i][0]  = C2[i][1]  = pack2s(0.f);
    }

    for (int pass = 0; pass < 4; pass++) {
        const float* src = (pass < 2) ? g_h : g_Sh;
        int koff = (pass & 1) * 32;
        __syncthreads();
        // stage 32 k x 128 n transposed
        for (int it = 0; it < 4; it++) {
            int f4 = tid + 256 * it;
            int n = f4 >> 3, kk = f4 & 7;
            float4 v = *(const float4*)&src[(base + n) * 64 + koff + 4 * kk];
            float* dst = &sA[(4 * kk) * 132 + n];
            dst[0] = v.x; dst[132] = v.y; dst[264] = v.z; dst[396] = v.w;
        }
        __syncthreads();
        int kg0 = koff;
        if (pass < 2) {
#pragma unroll 4
            for (int k = 0; k < 32; k++) {
                float4 a0 = *(const float4*)&sA[k * 132 + 8 * ty];
                float4 a1 = *(const float4*)&sA[k * 132 + 8 * ty + 4];
                ulonglong2 wW = *(const ulonglong2*)&sWw[(kg0 + k) * 64 + 4 * tx];
                ulonglong2 wI = *(const ulonglong2*)&sWxi[(kg0 + k) * 64 + 4 * tx];
                float av[8] = {a0.x, a0.y, a0.z, a0.w, a1.x, a1.y, a1.z, a1.w};
#pragma unroll
                for (int i = 0; i < 8; i++) {
                    u64 s = pack2s(av[i]);
                    fma2(C13[i][0], s, wW.x);
                    fma2(C13[i][1], s, wW.y);
                    fma2(C2[i][0],  s, wI.x);
                    fma2(C2[i][1],  s, wI.y);
                }
            }
        } else {
#pragma unroll 4
            for (int k = 0; k < 32; k++) {
                float4 a0 = *(const float4*)&sA[k * 132 + 8 * ty];
                float4 a1 = *(const float4*)&sA[k * 132 + 8 * ty + 4];
                ulonglong2 wJ = *(const ulonglong2*)&sWxj[(kg0 + k) * 64 + 4 * tx];
                float av[8] = {a0.x, a0.y, a0.z, a0.w, a1.x, a1.y, a1.z, a1.w};
#pragma unroll
                for (int i = 0; i < 8; i++) {
                    u64 s = pack2s(av[i]);
                    fma2(C13[i][0], s, wJ.x);
                    fma2(C13[i][1], s, wJ.y);
                }
            }
        }
    }

    // epilogue: affine terms + fdeg*C2, gelu, store
    ulonglong2 G[7];
#pragma unroll
    for (int p = 0; p < 7; p++) G[p] = *(const ulonglong2*)&sGeoB[p * 64 + 4 * tx];
#pragma unroll
    for (int i = 0; i < 8; i++) {
        const float* c = &sCoef[(8 * ty + i) * 8];
        u64 fd = pack2s(c[0]), mz = pack2s(c[1]), fgx = pack2s(c[2]),
            fgy = pack2s(c[3]), mx = pack2s(c[4]), my = pack2s(c[5]);
        u64 d0 = C13[i][0], d1 = C13[i][1];
        add2(d0, G[6].x);        add2(d1, G[6].y);        // bw
        fma2(d0, fd, G[5].x);    fma2(d1, fd, G[5].y);    // fdeg*bk
        fma2(d0, fd, C2[i][0]);  fma2(d1, fd, C2[i][1]);  // fdeg*(h@Wxi)
        fma2(d0, mz, G[0].x);    fma2(d1, mz, G[0].y);    // Σdist * geo0
        fma2(d0, fgx, G[1].x);   fma2(d1, fgx, G[1].y);
        fma2(d0, fgy, G[2].x);   fma2(d1, fgy, G[2].y);
        fma2(d0, mx, G[3].x);    fma2(d1, mx, G[3].y);
        fma2(d0, my, G[4].x);    fma2(d1, my, G[4].y);
        float2 lo = unpack2(d0), hi = unpack2(d1);
        *(float4*)&g_h2[(base + 8 * ty + i) * 64 + 4 * tx] =
            make_float4(gelu_f(lo.x), gelu_f(lo.y), gelu_f(hi.x), gelu_f(hi.y));
    }
}

// ============================================================================
// decode: out = gelu(h2@Wd1 + b1) @ Wd2 + b2   as tiled GEMM + reduction
// ============================================================================
#define DEC_SMEM_BYTES ((8448 + 8192 + 128 + 128 + 2176) * 4)
__global__ __launch_bounds__(256, 2) void k_decode(
    const float* __restrict__ Wd1, const float* __restrict__ bd1,
    const float* __restrict__ Wd2, const float* __restrict__ bd2,
    float* __restrict__ out) {
    extern __shared__ float sm[];
    float* sAt  = sm;           // [64][132] h2 transposed
    float* sW   = sm + 8448;    // [64][128]
    float* sB1  = sm + 16640;
    float* sW2v = sm + 16768;
    float* sRed = sm + 16896;   // [128][17]

    int tid = threadIdx.x;
    int base = blockIdx.x * 128;
    for (int it = 0; it < 8; it++) {
        int f4 = tid + 256 * it;
        int n = f4 >> 4, kk = f4 & 15;
        float4 v = *(const float4*)&g_h2[(base + n) * 64 + 4 * kk];
        float* dst = &sAt[(4 * kk) * 132 + n];
        dst[0] = v.x; dst[132] = v.y; dst[264] = v.z; dst[396] = v.w;
    }
    for (int i = tid; i < 8192; i += 256) sW[i] = Wd1[i];
    if (tid < 128) { sB1[tid] = bd1[tid]; sW2v[tid] = Wd2[tid]; }
    __syncthreads();

    int tx = tid & 15, ty = tid >> 4;
    u64 acc[8][4];  // [8 nodes][4 mid-pairs], mids 8*tx..8*tx+7
#pragma unroll
    for (int i = 0; i < 8; i++)
#pragma unroll
        for (int j = 0; j < 4; j++) acc[i][j] = pack2s(0.f);

#pragma unroll 4
    for (int k = 0; k < 64; k++) {
        float4 a0 = *(const float4*)&sAt[k * 132 + 8 * ty];
        float4 a1 = *(const float4*)&sAt[k * 132 + 8 * ty + 4];
        ulonglong2 w0 = *(const ulonglong2*)&sW[k * 128 + 8 * tx];
        ulonglong2 w1 = *(const ulonglong2*)&sW[k * 128 + 8 * tx + 4];
        float av[8] = {a0.x, a0.y, a0.z, a0.w, a1.x, a1.y, a1.z, a1.w};
#pragma unroll
        for (int i = 0; i < 8; i++) {
            u64 s = pack2s(av[i]);
            fma2(acc[i][0], s, w0.x);
            fma2(acc[i][1], s, w0.y);
            fma2(acc[i][2], s, w1.x);
            fma2(acc[i][3], s, w1.y);
        }
    }

    float b[8], w2[8];
#pragma unroll
    for (int j = 0; j < 8; j++) { b[j] = sB1[8 * tx + j]; w2[j] = sW2v[8 * tx + j]; }
#pragma unroll
    for (int i = 0; i < 8; i++) {
        float part = 0.f;
#pragma unroll
        for (int j = 0; j < 4; j++) {
            float2 v = unpack2(acc[i][j]);
            part += gelu_f(v.x + b[2 * j]) * w2[2 * j];
            part += gelu_f(v.y + b[2 * j + 1]) * w2[2 * j + 1];
        }
        sRed[(8 * ty + i) * 17 + tx] = part;
    }
    __syncthreads();
    if (tid < 128) {
        float s = 0.f;
        const float* r = &sRed[tid * 17];
#pragma unroll
        for (int t = 0; t < 16; t++) s += r[t];
        out[base + tid] = s + bd2[0];
    }
}

// ---------------- launch ----------------
extern "C" void kernel_launch(void* const* d_in, const int* in_sizes, int n_in,
                              void* d_out, int out_size) {
    const float*     x    = (const float*)d_in[0];
    const float*     grid = (const float*)d_in[1];
    const long long* ei   = (const long long*)d_in[2];  // may really be int32; detected
    const float* W1  = (const float*)d_in[3];
    const float* b1  = (const float*)d_in[4];
    const float* W2  = (const float*)d_in[5];
    const float* b2  = (const float*)d_in[6];
    const float* Wk  = (const float*)d_in[7];
    const float* bk  = (const float*)d_in[8];
    const float* Ww  = (const float*)d_in[9];
    const float* bw  = (const float*)d_in[10];
    const float* Wd1 = (const float*)d_in[11];
    const float* bd1 = (const float*)d_in[12];
    const float* Wd2 = (const float*)d_in[13];
    const float* bd2 = (const float*)d_in[14];
    float* out = (float*)d_out;

    cudaFuncSetAttribute(k_encode, cudaFuncAttributeMaxDynamicSharedMemorySize, ENC_SMEM_BYTES);
    cudaFuncSetAttribute(k_update, cudaFuncAttributeMaxDynamicSharedMemorySize, UPD_SMEM_BYTES);
    cudaFuncSetAttribute(k_decode, cudaFuncAttributeMaxDynamicSharedMemorySize, DEC_SMEM_BYTES);

    k_init<<<NN / 256, 256>>>(ei);
    k_encode<<<NN / 128, 256, ENC_SMEM_BYTES>>>(x, grid, W1, b1, W2, b2);
    k_scatter<<<EE / 2 / 256, 256>>>(ei);
    k_aggregate<<<(NN * 32) / 256, 256>>>(grid);
    k_update<<<NN / 128, 256, UPD_SMEM_BYTES>>>(grid, Wk, bk, Ww, bw);
    k_decode<<<NN / 128, 256, DEC_SMEM_BYTES>>>(Wd1, bd1, Wd2, bd2, out);
}